// round 2
// baseline (speedup 1.0000x reference)
#include <cuda_runtime.h>
#include <cstdint>

// Problem constants (fixed by the dataset)
#define NN 32
#define KK 32
#define TT 128
#define HH 768
#define H2 1536   // 2*H

// Output layout (flat float32 concat in reference return order)
#define OFF_SCORE 0
#define LEN_SCORE (NN*KK)                       // 1024
#define OFF_ENC   (OFF_SCORE + LEN_SCORE)       // 1024
#define LEN_ENC   (NN*TT*HH)                    // 3145728
#define OFF_MASK  (OFF_ENC + LEN_ENC)           // 3146752
#define LEN_MASK  (NN*TT)                       // 4096
#define OFF_USE   (OFF_MASK + LEN_MASK)         // 3150848
#define LEN_USE   (NN*HH)                       // 24576
#define OFF_IDX   (OFF_USE + LEN_USE)           // 3175424
#define LEN_IDX   (NN*TT)                       // 4096

// Scratch (no cudaMalloc allowed)
__device__ float g_cqk_pro[NN*HH];
__device__ float g_v[NN*HH];
__device__ float g_c[NN];

// ---- mask layout detection: byte-bool vs int32-bool --------------------
// For this dataset masks are all-True. byte layout => first u32 = 0x01010101,
// int32 layout => first u32 = 0x00000001.
__device__ __forceinline__ int mask_is_i32(const void* p) {
    return (*(const unsigned int*)p) == 1u;
}
__device__ __forceinline__ float read_mask(const void* p, int i, int i32f) {
    if (i32f) return ((const int*)p)[i] ? 1.0f : 0.0f;
    return ((const unsigned char*)p)[i] ? 1.0f : 0.0f;
}

// ======================================================================
// Kernel 1:
//   blocks [0,12):   cqk_pro[n][h] = sum_j cqk[n][j]*W_cqk[h][j] + b_cqk[h]
//                    (cqk = concat(ctx[:,2,:], tracked), shape [32,1536])
//   blocks [12,...): gather/copy of shifted_encoded / use / mask / index
// ======================================================================
#define NB_COPY 640

__global__ __launch_bounds__(256) void k1_cqkpro_and_gather(
    const float* __restrict__ ctx,       // [N,3,H]
    const float* __restrict__ trk,       // [N,H]
    const float* __restrict__ pe0,       // [N,K,T,H]
    const float* __restrict__ pe1,       // [N,K,H]
    const void*  __restrict__ pmask,     // [N,K,T] bool (byte or i32)
    const int*   __restrict__ ptok,      // [N,K,T] i32
    const int*   __restrict__ label,     // [N] i32
    const float* __restrict__ Wcqk,      // [H, 2H]
    const float* __restrict__ bcqk,      // [H]
    float* __restrict__ out)
{
    if (blockIdx.x < 12) {
        // ---- tiled GEMM: C[32 x 64-tile] over Ktot=1536, Ktile=64 ----
        __shared__ float As[32][64];      // cqk tile
        __shared__ float Ws[64][65];      // W tile, padded for conflict-free
        const int t  = threadIdx.x;
        const int h0 = blockIdx.x * 64;
        const int hi = t & 63;
        const int ng = t >> 6;            // 0..3 (row group of 8)

        float acc[8];
        #pragma unroll
        for (int r = 0; r < 8; r++) acc[r] = 0.0f;

        for (int k0 = 0; k0 < H2; k0 += 64) {
            // load cqk tile (2048 elems, 8/thread)
            #pragma unroll
            for (int i = t; i < 32*64; i += 256) {
                int n = i >> 6, k = i & 63;
                int j = k0 + k;
                As[n][k] = (j < HH) ? ctx[n*3*HH + 2*HH + j]
                                    : trk[n*HH + (j - HH)];
            }
            // load W tile (4096 elems, 16/thread), coalesced along k
            #pragma unroll
            for (int i = t; i < 64*64; i += 256) {
                int hh = i >> 6, k = i & 63;
                Ws[hh][k] = Wcqk[(size_t)(h0 + hh) * H2 + k0 + k];
            }
            __syncthreads();

            #pragma unroll 8
            for (int k = 0; k < 64; k++) {
                float w = Ws[hi][k];
                #pragma unroll
                for (int r = 0; r < 8; r++)
                    acc[r] += As[ng*8 + r][k] * w;
            }
            __syncthreads();
        }
        float b = bcqk[h0 + hi];
        #pragma unroll
        for (int r = 0; r < 8; r++)
            g_cqk_pro[(ng*8 + r)*HH + h0 + hi] = acc[r] + b;
        return;
    }

    // ---------------- gather / copy part ----------------
    const int i32f = mask_is_i32(pmask);
    const float4* pe0_4 = (const float4*)pe0;
    const float4* pe1_4 = (const float4*)pe1;
    float4* out4 = (float4*)out;

    // work ranges (flat):
    //   [0, R0)         : enc as float4     R0 = LEN_ENC/4  = 786432
    //   [R0, R1)        : use as float4     +LEN_USE/4 (6144)
    //   [R1, R2)        : mask scalar       +4096
    //   [R2, R3)        : tok  scalar       +4096
    const int R0 = LEN_ENC / 4;
    const int R1 = R0 + LEN_USE / 4;
    const int R2 = R1 + LEN_MASK;
    const int R3 = R2 + LEN_IDX;

    const int gid    = blockIdx.x - 12;
    const int stride = NB_COPY * 256;

    for (int idx = gid * 256 + threadIdx.x; idx < R3; idx += stride) {
        if (idx < R0) {
            // shifted_encoded: per-n contiguous chunk of T*H/4 = 24576 float4
            int n     = idx / 24576;
            int local = idx - n * 24576;
            int lab   = label[n];
            out4[OFF_ENC/4 + idx] = pe0_4[(size_t)(n*KK + lab) * 24576 + local];
        } else if (idx < R1) {
            int j     = idx - R0;          // [0, 6144)
            int n     = j / 192;           // H/4 = 192
            int local = j - n * 192;
            int lab   = label[n];
            out4[OFF_USE/4 + j] = pe1_4[(n*KK + lab) * 192 + local];
        } else if (idx < R2) {
            int j   = idx - R1;            // [0, 4096)
            int n   = j / TT;
            int tt  = j - n * TT;
            int lab = label[n];
            out[OFF_MASK + j] = read_mask(pmask, (n*KK + lab)*TT + tt, i32f);
        } else {
            int j   = idx - R2;
            int n   = j / TT;
            int tt  = j - n * TT;
            int lab = label[n];
            out[OFF_IDX + j] = (float)ptok[(n*KK + lab)*TT + tt];
        }
    }
}

// ======================================================================
// Kernel 2:
//   blocks [0,12): v[n][h] = sum_g cqk_pro[n][g] * W_k[g][h]
//   block 12:      c[n] = sum_g b_k[g] * cqk_pro[n][g]
// ======================================================================
__global__ __launch_bounds__(256) void k2_v_and_c(
    const float* __restrict__ Wk,   // [H,H] row-major (g, h)
    const float* __restrict__ bk)   // [H]
{
    if (blockIdx.x < 12) {
        __shared__ float Ps[32][64];
        __shared__ float Ws[64][64];   // [g][h] — stride 64, conflict-free
        const int t  = threadIdx.x;
        const int h0 = blockIdx.x * 64;
        const int hi = t & 63;
        const int ng = t >> 6;

        float acc[8];
        #pragma unroll
        for (int r = 0; r < 8; r++) acc[r] = 0.0f;

        for (int k0 = 0; k0 < HH; k0 += 64) {
            #pragma unroll
            for (int i = t; i < 32*64; i += 256) {
                int n = i >> 6, k = i & 63;
                Ps[n][k] = g_cqk_pro[n*HH + k0 + k];
            }
            #pragma unroll
            for (int i = t; i < 64*64; i += 256) {
                int g = i >> 6, hh = i & 63;
                Ws[g][hh] = Wk[(size_t)(k0 + g)*HH + h0 + hh];
            }
            __syncthreads();

            #pragma unroll 8
            for (int g = 0; g < 64; g++) {
                float w = Ws[g][hi];
                #pragma unroll
                for (int r = 0; r < 8; r++)
                    acc[r] += Ps[ng*8 + r][g] * w;
            }
            __syncthreads();
        }
        #pragma unroll
        for (int r = 0; r < 8; r++)
            g_v[(ng*8 + r)*HH + h0 + hi] = acc[r];
        return;
    }

    // block 12: c[n] — 8 warps, each handles n = w, w+8, ...
    const int w    = threadIdx.x >> 5;
    const int lane = threadIdx.x & 31;
    for (int n = w; n < NN; n += 8) {
        float s = 0.0f;
        for (int g = lane; g < HH; g += 32)
            s += bk[g] * g_cqk_pro[n*HH + g];
        #pragma unroll
        for (int o = 16; o; o >>= 1) s += __shfl_xor_sync(0xFFFFFFFFu, s, o);
        if (lane == 0) g_c[n] = s;
    }
}

// ======================================================================
// Kernel 3: score[n][k] = dot(pe1[n,k,:], v[n,:]) + c[n], ck-masked
//   1024 warps, one per (n,k). Grid 128 x 256.
// ======================================================================
__global__ __launch_bounds__(256) void k3_score(
    const float* __restrict__ pe1,
    const void*  __restrict__ ckmask,
    float* __restrict__ out)
{
    const int w    = blockIdx.x * 8 + (threadIdx.x >> 5);
    const int lane = threadIdx.x & 31;
    const int n = w >> 5;
    const int k = w & 31;

    const float* a = pe1 + (size_t)(n*KK + k) * HH;
    const float* b = g_v + n*HH;

    float s = 0.0f;
    #pragma unroll
    for (int i = 0; i < HH/32; i++)
        s += a[lane + 32*i] * b[lane + 32*i];
    #pragma unroll
    for (int o = 16; o; o >>= 1) s += __shfl_xor_sync(0xFFFFFFFFu, s, o);

    if (lane == 0) {
        int   i32f = mask_is_i32(ckmask);
        float m    = read_mask(ckmask, n*KK + k, i32f);
        out[OFF_SCORE + n*KK + k] = (m != 0.0f) ? (s + g_c[n]) : -1e20f;
    }
}

// ======================================================================
extern "C" void kernel_launch(void* const* d_in, const int* in_sizes, int n_in,
                              void* d_out, int out_size)
{
    const float* ctx   = (const float*)d_in[0];   // contexts_encoded_1 [N,3,H]
    const float* trk   = (const float*)d_in[1];   // tracked_knowledge_use [N,H]
    const float* pe0   = (const float*)d_in[2];   // pool_encoded_0 [N,K,T,H]
    const float* pe1   = (const float*)d_in[3];   // pool_encoded_1 [N,K,H]
    const void*  pmask = (const void*)d_in[4];    // pool_mask [N,K,T] bool
    const void*  ckm   = (const void*)d_in[5];    // ck_mask [N,K] bool
    const int*   label = (const int*)d_in[6];     // label [N]
    const int*   ptok  = (const int*)d_in[7];     // pool_tokens [N,K,T]
    const float* Wcqk  = (const float*)d_in[8];   // [H,2H]
    const float* bcqk  = (const float*)d_in[9];   // [H]
    const float* Wk    = (const float*)d_in[10];  // [H,H]
    const float* bk    = (const float*)d_in[11];  // [H]
    float* out = (float*)d_out;

    k1_cqkpro_and_gather<<<12 + NB_COPY, 256>>>(ctx, trk, pe0, pe1, pmask,
                                                ptok, label, Wcqk, bcqk, out);
    k2_v_and_c<<<13, 256>>>(Wk, bk);
    k3_score<<<128, 256>>>(pe1, ckm, out);
}

// round 7
// speedup vs baseline: 3.6529x; 3.6529x over previous
#include <cuda_runtime.h>
#include <cstdint>

// Problem constants (fixed by the dataset)
#define NN 32
#define KK 32
#define TT 128
#define HH 768
#define H2 1536   // 2*H

// Output layout (flat float32 concat in reference return order)
#define OFF_SCORE 0
#define LEN_SCORE (NN*KK)                       // 1024
#define OFF_ENC   (OFF_SCORE + LEN_SCORE)       // 1024
#define LEN_ENC   (NN*TT*HH)                    // 3145728
#define OFF_MASK  (OFF_ENC + LEN_ENC)           // 3146752
#define LEN_MASK  (NN*TT)                       // 4096
#define OFF_USE   (OFF_MASK + LEN_MASK)         // 3150848
#define LEN_USE   (NN*HH)                       // 24576
#define OFF_IDX   (OFF_USE + LEN_USE)           // 3175424
#define LEN_IDX   (NN*TT)                       // 4096

// GEMM tiling: 12 h-tiles of 64, 12 k-splits
#define NSPLIT 12
#define G1_KC  128   // GEMM1: K=1536 -> 12 chunks of 128
#define G2_KC  64    // GEMM2: K=768  -> 12 chunks of 64

// Scratch (no cudaMalloc allowed)
__device__ float g_p1[NSPLIT*NN*HH];   // GEMM1 partials (bias folded into split 0)
__device__ float g_p2[NSPLIT*NN*HH];   // GEMM2 partials

// ---- mask layout detection: byte-bool vs int32-bool --------------------
__device__ __forceinline__ int mask_is_i32(const void* p) {
    return (*(const unsigned int*)p) == 1u;
}
__device__ __forceinline__ float read_mask(const void* p, int i, int i32f) {
    if (i32f) return ((const int*)p)[i] ? 1.0f : 0.0f;
    return ((const unsigned char*)p)[i] ? 1.0f : 0.0f;
}

// ======================================================================
// Kernel 1:
//   blocks [0,144):    GEMM1 partial: p1[ks][n][h] = sum_{k in chunk}
//                      cqk[n][k]*W_cqk[h][k]   (+bias on ks==0)
//   blocks [144,688):  gather/copy (enc / use / mask / idx)
// ======================================================================
#define NB_G1   (NSPLIT*NSPLIT)       // 144
#define NB_ENC  512                   // enc copy: 16 blocks per n
#define NB_TAIL NN                    // per-n small copies
#define NB_K1   (NB_G1 + NB_ENC + NB_TAIL)

__global__ __launch_bounds__(256) void k1_gemm1_and_gather(
    const float* __restrict__ ctx,       // [N,3,H]
    const float* __restrict__ trk,       // [N,H]
    const float* __restrict__ pe0,       // [N,K,T,H]
    const float* __restrict__ pe1,       // [N,K,H]
    const void*  __restrict__ pmask,     // [N,K,T] bool (byte or i32)
    const int*   __restrict__ ptok,      // [N,K,T] i32
    const int*   __restrict__ label,     // [N] i32
    const float* __restrict__ Wcqk,      // [H, 2H]
    const float* __restrict__ bcqk,      // [H]
    float* __restrict__ out)
{
    if (blockIdx.x < NB_G1) {
        __shared__ float As[G1_KC*32];    // [k][n], 16B-group swizzled
        __shared__ float Ws[G1_KC*64];    // [k][h], pair swizzled
        const int bt = blockIdx.x;
        const int ks = bt / NSPLIT;
        const int h0 = (bt % NSPLIT) * 64;
        const int k0 = ks * G1_KC;
        const int t  = threadIdx.x;

        // As: cqk[n][k0+kk] -> As[kk][n] (swizzle 16B groups along n)
        for (int i = t; i < 32*G1_KC; i += 256) {
            int n  = i >> 7;
            int kk = i & 127;
            int j  = k0 + kk;
            float v = (j < HH) ? ctx[n*3*HH + 2*HH + j] : trk[n*HH + (j - HH)];
            int grp = (n >> 2) ^ (kk & 7);
            As[kk*32 + grp*4 + (n & 3)] = v;
        }
        // Ws: Wcqk[h0+hh][k0+kk] -> Ws[kk][hh] (pair swizzle along h)
        for (int i = t; i < 64*G1_KC; i += 256) {
            int hh = i >> 7;
            int kk = i & 127;
            float w = Wcqk[(size_t)(h0 + hh) * H2 + k0 + kk];
            int p  = hh >> 1, q = hh & 1;
            int pp = p ^ (kk & 31);
            Ws[kk*64 + pp*2 + q] = w;
        }
        __syncthreads();

        const int rg = t >> 5;        // 0..7 -> rows rg*4..rg*4+3
        const int cp = t & 31;        // col pair
        float acc[4][2] = {{0,0},{0,0},{0,0},{0,0}};

        #pragma unroll 8
        for (int k = 0; k < G1_KC; k++) {
            const float4 a = *(const float4*)&As[k*32 + ((rg ^ (k & 7)) << 2)];
            const float2 w = *(const float2*)&Ws[k*64 + ((cp ^ (k & 31)) << 1)];
            acc[0][0] += a.x*w.x; acc[0][1] += a.x*w.y;
            acc[1][0] += a.y*w.x; acc[1][1] += a.y*w.y;
            acc[2][0] += a.z*w.x; acc[2][1] += a.z*w.y;
            acc[3][0] += a.w*w.x; acc[3][1] += a.w*w.y;
        }

        float b0 = 0.0f, b1 = 0.0f;
        if (ks == 0) { b0 = bcqk[h0 + cp*2]; b1 = bcqk[h0 + cp*2 + 1]; }
        #pragma unroll
        for (int r = 0; r < 4; r++) {
            float2 st; st.x = acc[r][0] + b0; st.y = acc[r][1] + b1;
            *(float2*)&g_p1[ks*NN*HH + (rg*4 + r)*HH + h0 + cp*2] = st;
        }
        return;
    }

    // ---------------- gather / copy part ----------------
    const int gid = blockIdx.x - NB_G1;
    const int t   = threadIdx.x;
    const float4* pe0_4 = (const float4*)pe0;
    const float4* pe1_4 = (const float4*)pe1;
    float4* out4 = (float4*)out;

    if (gid < NB_ENC) {
        // shifted_encoded: per n, 24576 float4; 16 blocks per n, 1536 f4 each
        const int n    = gid >> 4;
        const int part = gid & 15;
        const int lab  = label[n];
        const float4* src = pe0_4 + (size_t)(n*KK + lab) * 24576 + part * 1536;
        float4*       dst = out4 + OFF_ENC/4 + (size_t)n * 24576 + part * 1536;
        float4 r[6];
        #pragma unroll
        for (int j = 0; j < 6; j++) r[j] = src[t + 256*j];
        #pragma unroll
        for (int j = 0; j < 6; j++) dst[t + 256*j] = r[j];
    } else {
        // per-n small copies: use (192 f4), mask (128), idx (128)
        const int n   = gid - NB_ENC;
        const int lab = label[n];
        if (t < 192)
            out4[OFF_USE/4 + n*192 + t] = pe1_4[(n*KK + lab)*192 + t];
        if (t < 128) {
            const int i32f = mask_is_i32(pmask);
            out[OFF_MASK + n*TT + t] = read_mask(pmask, (n*KK + lab)*TT + t, i32f);
            out[OFF_IDX  + n*TT + t] = (float)ptok[(n*KK + lab)*TT + t];
        }
    }
}

// ======================================================================
// Kernel 2: GEMM2 partial: p2[ks][n][h] = sum_{g in chunk} cqk_pro[n][g]*W_k[g][h]
//   cqk_pro reduced from g_p1 on the fly while loading the A tile.
// ======================================================================
__global__ __launch_bounds__(256) void k2_gemm2(
    const float* __restrict__ Wk)   // [H,H] row-major (g, h)
{
    __shared__ float As[G2_KC*32];
    __shared__ float Ws[G2_KC*64];
    const int bt = blockIdx.x;
    const int ks = bt / NSPLIT;
    const int h0 = (bt % NSPLIT) * 64;
    const int k0 = ks * G2_KC;
    const int t  = threadIdx.x;

    // A tile: cqk_pro[n][k0+kk] = sum_s p1[s][n][k0+kk]
    for (int i = t; i < 32*G2_KC; i += 256) {
        int n  = i >> 6;
        int kk = i & 63;
        const float* p = g_p1 + n*HH + k0 + kk;
        float v = 0.0f;
        #pragma unroll
        for (int s = 0; s < NSPLIT; s++) v += p[s*NN*HH];
        int grp = (n >> 2) ^ (kk & 7);
        As[kk*32 + grp*4 + (n & 3)] = v;
    }
    // W tile: Wk[k0+gg][h0+hh] -> Ws[gg][hh] (pair swizzle along h; coalesced read)
    for (int i = t; i < 64*G2_KC; i += 256) {
        int gg = i >> 6;
        int hh = i & 63;
        float w = Wk[(size_t)(k0 + gg)*HH + h0 + hh];
        int p  = hh >> 1, q = hh & 1;
        int pp = p ^ (gg & 31);
        Ws[gg*64 + pp*2 + q] = w;
    }
    __syncthreads();

    const int rg = t >> 5;
    const int cp = t & 31;
    float acc[4][2] = {{0,0},{0,0},{0,0},{0,0}};

    #pragma unroll 8
    for (int k = 0; k < G2_KC; k++) {
        const float4 a = *(const float4*)&As[k*32 + ((rg ^ (k & 7)) << 2)];
        const float2 w = *(const float2*)&Ws[k*64 + ((cp ^ (k & 31)) << 1)];
        acc[0][0] += a.x*w.x; acc[0][1] += a.x*w.y;
        acc[1][0] += a.y*w.x; acc[1][1] += a.y*w.y;
        acc[2][0] += a.z*w.x; acc[2][1] += a.z*w.y;
        acc[3][0] += a.w*w.x; acc[3][1] += a.w*w.y;
    }
    #pragma unroll
    for (int r = 0; r < 4; r++) {
        float2 st; st.x = acc[r][0]; st.y = acc[r][1];
        *(float2*)&g_p2[ks*NN*HH + (rg*4 + r)*HH + h0 + cp*2] = st;
    }
}

// ======================================================================
// Kernel 3: one block per n.
//   - reduce v[n][:] from g_p2 into smem
//   - c[n] = sum_g bk[g] * cqk_pro[n][g]   (cqk_pro re-reduced from g_p1, L2)
//   - score[n][k] = dot(pe1[n,k,:], v) + c[n], ck-masked
// ======================================================================
__global__ __launch_bounds__(256) void k3_reduce_score(
    const float* __restrict__ pe1,
    const void*  __restrict__ ckmask,
    const float* __restrict__ bk,
    float* __restrict__ out)
{
    __shared__ float vs[HH];
    __shared__ float red[8];
    __shared__ float cn_s;
    const int n    = blockIdx.x;
    const int t    = threadIdx.x;
    const int w    = t >> 5;
    const int lane = t & 31;

    // v reduction + c partial
    float cpart = 0.0f;
    #pragma unroll
    for (int h = t; h < HH; h += 256) {
        const float* p2 = g_p2 + n*HH + h;
        const float* p1 = g_p1 + n*HH + h;
        float v = 0.0f, q = 0.0f;
        #pragma unroll
        for (int s = 0; s < NSPLIT; s++) { v += p2[s*NN*HH]; q += p1[s*NN*HH]; }
        vs[h] = v;
        cpart += bk[h] * q;
    }
    #pragma unroll
    for (int o = 16; o; o >>= 1) cpart += __shfl_xor_sync(0xFFFFFFFFu, cpart, o);
    if (lane == 0) red[w] = cpart;
    __syncthreads();
    if (t == 0) {
        float c = 0.0f;
        #pragma unroll
        for (int i = 0; i < 8; i++) c += red[i];
        cn_s = c;
    }
    __syncthreads();

    // scores: warp w handles k = w*4 .. w*4+3
    const float4* vs4 = (const float4*)vs;
    const int i32f = mask_is_i32(ckmask);
    #pragma unroll
    for (int kk = 0; kk < 4; kk++) {
        const int k = w*4 + kk;
        const float4* a = (const float4*)(pe1 + (size_t)(n*KK + k) * HH);
        float s = 0.0f;
        #pragma unroll
        for (int i = 0; i < 6; i++) {
            float4 x = a[lane + 32*i];
            float4 v = vs4[lane + 32*i];
            s += x.x*v.x + x.y*v.y + x.z*v.z + x.w*v.w;
        }
        #pragma unroll
        for (int o = 16; o; o >>= 1) s += __shfl_xor_sync(0xFFFFFFFFu, s, o);
        if (lane == 0) {
            float m = read_mask(ckmask, n*KK + k, i32f);
            out[OFF_SCORE + n*KK + k] = (m != 0.0f) ? (s + cn_s) : -1e20f;
        }
    }
}

// ======================================================================
extern "C" void kernel_launch(void* const* d_in, const int* in_sizes, int n_in,
                              void* d_out, int out_size)
{
    const float* ctx   = (const float*)d_in[0];   // contexts_encoded_1 [N,3,H]
    const float* trk   = (const float*)d_in[1];   // tracked_knowledge_use [N,H]
    const float* pe0   = (const float*)d_in[2];   // pool_encoded_0 [N,K,T,H]
    const float* pe1   = (const float*)d_in[3];   // pool_encoded_1 [N,K,H]
    const void*  pmask = (const void*)d_in[4];    // pool_mask [N,K,T] bool
    const void*  ckm   = (const void*)d_in[5];    // ck_mask [N,K] bool
    const int*   label = (const int*)d_in[6];     // label [N]
    const int*   ptok  = (const int*)d_in[7];     // pool_tokens [N,K,T]
    const float* Wcqk  = (const float*)d_in[8];   // [H,2H]
    const float* bcqk  = (const float*)d_in[9];   // [H]
    const float* Wk    = (const float*)d_in[10];  // [H,H]
    const float* bk    = (const float*)d_in[11];  // [H]
    float* out = (float*)d_out;

    k1_gemm1_and_gather<<<NB_K1, 256>>>(ctx, trk, pe0, pe1, pmask,
                                        ptok, label, Wcqk, bcqk, out);
    k2_gemm2<<<NB_G1, 256>>>(Wk);
    k3_reduce_score<<<NN, 256>>>(pe1, ckm, bk, out);
}